// round 16
// baseline (speedup 1.0000x reference)
#include <cuda_runtime.h>
#include <math.h>
#include <stdint.h>

// ---------------- problem constants ----------------
#define BATCH   4
#define CDIM    512
#define HWTOK   4096          // 64*64
#define GWIN    1024          // 32*32 windows per batch
#define HDIM    256
#define LDIM    256
#define ATT_SCALE 0.125f      // 64^-0.5

#define LDF 20                // padded row stride (floats) for 16-k GEMM tiles
#define LDK 68                // padded row stride for 64-wide attention tiles
#define GSTG (128 * LDF)      // floats per stage per tensor
#define GEMM_SMEM (3 * GSTG * 2 * 4)   // 3-stage A+B, bytes (61440)

// weight scratch offsets (floats) — transposed [n][k] layouts
#define W_QKV 0               // [768][512]
#define W_LQ  393216          // [256][512]
#define W_LKV 524288          // [512][512]
#define W_HP  786432          // [256][256]
#define W_LP  851968          // [256][256]
#define W_TOT 917504

// ---------------- scratch (device globals; no allocation allowed) ----------------
__device__ float g_xr[(size_t)BATCH * HWTOK * CDIM];          // x transposed+rounded: [b][tok][c]
__device__ float g_wr[W_TOT];                                 // transposed+rounded weights
__device__ float g_pooled[BATCH * GWIN * CDIM];               // [bg][c], rounded
__device__ float g_qkvq[(size_t)BATCH * HWTOK * 1024];        // [tok][qkv_hi 768 fp32 | q_lo 256 rounded]
__device__ float g_lk[BATCH * GWIN * 256];                    // lo K: [bg][256], rounded
__device__ float g_lvT[BATCH * 4 * 64 * GWIN];                // lo V transposed: [(b*4+h)*64+d][g], rounded
__device__ float g_hiat[(size_t)BATCH * HWTOK * HDIM];        // hi attn out, rounded
__device__ float g_loat[(size_t)BATCH * HWTOK * LDIM];        // lo attn out, rounded

// ---------------- helpers ----------------
__device__ __forceinline__ float to_tf32(float x) {
    uint32_t r;
    asm("cvt.rna.tf32.f32 %0, %1;" : "=r"(r) : "f"(x));
    return __uint_as_float(r);
}
__device__ __forceinline__ float4 to_tf32_4(float4 v) {
    v.x = to_tf32(v.x); v.y = to_tf32(v.y); v.z = to_tf32(v.z); v.w = to_tf32(v.w);
    return v;
}
__device__ __forceinline__ void cp16(void* dst, const void* src) {
    uint32_t d = (uint32_t)__cvta_generic_to_shared(dst);
    asm volatile("cp.async.cg.shared.global [%0], [%1], 16;\n" :: "r"(d), "l"(src) : "memory");
}
#define CP_COMMIT asm volatile("cp.async.commit_group;\n" ::: "memory")
#define CP_WAIT1  asm volatile("cp.async.wait_group 1;\n" ::: "memory")
#define CP_WAIT2  asm volatile("cp.async.wait_group 2;\n" ::: "memory")

__device__ __forceinline__ void ldsm4(uint32_t& r0, uint32_t& r1, uint32_t& r2, uint32_t& r3,
                                      const float* p) {
    uint32_t a = (uint32_t)__cvta_generic_to_shared(p);
    asm volatile("ldmatrix.sync.aligned.m8n8.x4.shared.b16 {%0,%1,%2,%3}, [%4];\n"
                 : "=r"(r0), "=r"(r1), "=r"(r2), "=r"(r3) : "r"(a));
}

// D = A(16x8) * B(8x8) + D, tf32 in, f32 out.
__device__ __forceinline__ void mma_tf32(float4& c, const uint32_t* a, const uint32_t* b) {
    asm volatile(
        "mma.sync.aligned.m16n8k8.row.col.f32.tf32.tf32.f32 "
        "{%0,%1,%2,%3}, {%4,%5,%6,%7}, {%8,%9}, {%0,%1,%2,%3};\n"
        : "+f"(c.x), "+f"(c.y), "+f"(c.z), "+f"(c.w)
        : "r"(a[0]), "r"(a[1]), "r"(a[2]), "r"(a[3]), "r"(b[0]), "r"(b[1]));
}

// ---------------- tiled transpose + tf32 round: in[r][c] -> out[c][r] ----------------
__global__ void transpose_round(const float* __restrict__ in, float* __restrict__ out,
                                int rows, int cols)
{
    __shared__ float t[32][33];
    size_t plane = (size_t)rows * cols;
    in  += (size_t)blockIdx.z * plane;
    out += (size_t)blockIdx.z * plane;
    int c0 = blockIdx.x * 32, r0 = blockIdx.y * 32;
    int tx = threadIdx.x & 31, ty = threadIdx.x >> 5;
#pragma unroll
    for (int i = 0; i < 4; i++)
        t[ty + i * 8][tx] = to_tf32(in[(size_t)(r0 + ty + i * 8) * cols + c0 + tx]);
    __syncthreads();
#pragma unroll
    for (int i = 0; i < 4; i++)
        out[(size_t)(c0 + ty + i * 8) * rows + r0 + tx] = t[tx][ty + i * 8];
}

// ---------------- all 5 weight transposes in one launch (z-indexed) ----------------
__global__ void transpose_round_w(const float* __restrict__ w1, const float* __restrict__ w2,
                                  const float* __restrict__ w3, const float* __restrict__ w4,
                                  const float* __restrict__ w5)
{
    __shared__ float t[32][33];
    const float* in; float* out; int rows, cols;
    switch (blockIdx.z) {
        case 0:  in = w1; out = g_wr + W_QKV; rows = CDIM; cols = 768; break;
        case 1:  in = w2; out = g_wr + W_LQ;  rows = CDIM; cols = 256; break;
        case 2:  in = w3; out = g_wr + W_LKV; rows = CDIM; cols = 512; break;
        case 3:  in = w4; out = g_wr + W_HP;  rows = 256;  cols = 256; break;
        default: in = w5; out = g_wr + W_LP;  rows = 256;  cols = 256; break;
    }
    int c0 = blockIdx.x * 32, r0 = blockIdx.y * 32;
    if (c0 >= cols || r0 >= rows) return;
    int tx = threadIdx.x & 31, ty = threadIdx.x >> 5;
#pragma unroll
    for (int i = 0; i < 4; i++)
        t[ty + i * 8][tx] = to_tf32(in[(size_t)(r0 + ty + i * 8) * cols + c0 + tx]);
    __syncthreads();
#pragma unroll
    for (int i = 0; i < 4; i++)
        out[(size_t)(c0 + ty + i * 8) * rows + r0 + tx] = t[tx][ty + i * 8];
}

// ---------------- window pooling -> g_pooled [bg][c], rounded ----------------
__global__ void pool_kernel(const float* __restrict__ x)
{
    __shared__ float t[32][33];
    int bg0 = blockIdx.x * 32, c0 = blockIdx.y * 32;
    int tx = threadIdx.x & 31, ty = threadIdx.x >> 5;
    int b = bg0 >> 10;
    int gbase = bg0 & 1023;
#pragma unroll
    for (int i = 0; i < 4; i++) {
        int c = c0 + ty + i * 8;
        int g = gbase + tx;
        int gh = g >> 5, gw = g & 31;
        const float* p = x + ((size_t)b * CDIM + c) * HWTOK + gh * 128 + gw * 2;
        t[ty + i * 8][tx] = to_tf32(0.25f * (p[0] + p[1] + p[64] + p[65]));
    }
    __syncthreads();
#pragma unroll
    for (int i = 0; i < 4; i++) {
        int bg = bg0 + ty + i * 8;
        g_pooled[(size_t)bg * CDIM + c0 + tx] = t[tx][ty + i * 8];
    }
}

// ---------------- tf32 GEMM, 3-stage cp.async + ldmatrix ----------------
// A row-major [m][K] pre-rounded. B row-major [n][K] pre-rounded (transposed weights).
// 128x128 tile, K-slab 16, 256 threads = 8 warps (2m x 4n), warp tile 64x32.
// mode 0: C row-major, round cols >= roundCol
// mode 1: lo-kv: cols<256 -> g_lk[m][col]; cols>=256 -> g_lvT transposed (all rounded)
// mode 2: dual projection (z=0: A/B1/bias/cOff=0; z=1: A2/B2/bias2/cOff=256),
//         bias + transposed store into (B,512,64,64)
__global__ __launch_bounds__(256, 3) void gemm_tf32(
    const float* __restrict__ A, int lda, size_t aBatch,
    const float* __restrict__ B1, const float* __restrict__ B2, int nsplit,
    int K, float* __restrict__ C, int ldc, size_t cBatch,
    int mode, int roundCol, const float* __restrict__ bias, int cOff,
    const float* __restrict__ A2, const float* __restrict__ bias2)
{
    extern __shared__ float smg[];
    float* As = smg;                 // [3][GSTG]
    float* Bs = smg + 3 * GSTG;      // [3][GSTG]

    int n0 = blockIdx.x * 128, m0 = blockIdx.y * 128;
    const float* Ab; float* Cb; const float* Bw; int nb;
    const float* bi = bias; int co = cOff;
    if (mode == 2) {
        Cb = C; nb = n0;
        if (blockIdx.z == 0) { Ab = A;  Bw = B1; }
        else                 { Ab = A2; Bw = B2; bi = bias2; co = 256; }
    } else {
        Ab = A + (size_t)blockIdx.z * aBatch;
        Cb = C + (size_t)blockIdx.z * cBatch;
        if (n0 < nsplit) { Bw = B1; nb = n0; }
        else             { Bw = B2; nb = n0 - nsplit; }
    }

    int tid  = threadIdx.x;
    int lane = tid & 31, wid = tid >> 5;
    int g = lane >> 2, tig = lane & 3;
    int wm0 = (wid & 1) * 64;
    int wn0 = (wid >> 1) * 32;
    // ldmatrix lane addressing
    int arow  = lane & 15,               akcol = (lane >> 4) << 2;               // A (m16 x k8)
    int bnrow = (lane & 7) | ((lane >> 4) << 3), bkcol = ((lane >> 3) & 1) << 2; // B (n16 x k8)
    // staging
    int sm = tid >> 2, skq = (tid & 3) * 4;

    float4 acc[4][4];
#pragma unroll
    for (int i = 0; i < 4; i++)
#pragma unroll
        for (int j = 0; j < 4; j++) acc[i][j] = make_float4(0.f, 0.f, 0.f, 0.f);

#define STAGE(k0, st) {                                                                  \
    float* Ad = As + (st) * GSTG;                                                        \
    float* Bd = Bs + (st) * GSTG;                                                        \
    cp16(&Ad[sm * LDF + skq],        &Ab[(size_t)(m0 + sm) * lda + (k0) + skq]);         \
    cp16(&Ad[(sm + 64) * LDF + skq], &Ab[(size_t)(m0 + sm + 64) * lda + (k0) + skq]);    \
    cp16(&Bd[sm * LDF + skq],        &Bw[(size_t)(nb + sm) * K + (k0) + skq]);           \
    cp16(&Bd[(sm + 64) * LDF + skq], &Bw[(size_t)(nb + sm + 64) * K + (k0) + skq]); }

    int nIter = K >> 4;                 // >= 16 for all call sites
    STAGE(0, 0);  CP_COMMIT;
    STAGE(16, 1); CP_COMMIT;

#pragma unroll 1
    for (int it = 0; it < nIter; it++) {
        if (it + 2 < nIter) { int k0 = (it + 2) << 4; STAGE(k0, (it + 2) % 3); }
        CP_COMMIT;
        CP_WAIT2;
        __syncthreads();
        const float* Ac = As + (it % 3) * GSTG;
        const float* Bc = Bs + (it % 3) * GSTG;
#pragma unroll
        for (int ks = 0; ks < 16; ks += 8) {
            uint32_t a[4][4], b[4][2];
#pragma unroll
            for (int mf = 0; mf < 4; mf++)
                ldsm4(a[mf][0], a[mf][1], a[mf][2], a[mf][3],
                      &Ac[(wm0 + mf * 16 + arow) * LDF + ks + akcol]);
#pragma unroll
            for (int nfp = 0; nfp < 2; nfp++) {
                uint32_t r0, r1, r2, r3;
                ldsm4(r0, r1, r2, r3, &Bc[(wn0 + nfp * 16 + bnrow) * LDF + ks + bkcol]);
                b[2 * nfp][0] = r0; b[2 * nfp][1] = r1;
                b[2 * nfp + 1][0] = r2; b[2 * nfp + 1][1] = r3;
            }
#pragma unroll
            for (int mf = 0; mf < 4; mf++)
#pragma unroll
                for (int nf = 0; nf < 4; nf++)
                    mma_tf32(acc[mf][nf], a[mf], b[nf]);
        }
        __syncthreads();
    }
#undef STAGE

    if (mode == 0) {
        bool doRound = (n0 >= roundCol);
#pragma unroll
        for (int mf = 0; mf < 4; mf++) {
            int row = m0 + wm0 + mf * 16 + g;
#pragma unroll
            for (int nf = 0; nf < 4; nf++) {
                int col = n0 + wn0 + nf * 8 + 2 * tig;
                float4 v = acc[mf][nf];
                if (doRound) v = to_tf32_4(v);
                *(float2*)&Cb[(size_t)row * ldc + col]       = make_float2(v.x, v.y);
                *(float2*)&Cb[(size_t)(row + 8) * ldc + col] = make_float2(v.z, v.w);
            }
        }
    } else if (mode == 1) {
        bool isV = (n0 >= 256);
#pragma unroll
        for (int mf = 0; mf < 4; mf++) {
            int m = m0 + wm0 + mf * 16 + g;
#pragma unroll
            for (int nf = 0; nf < 4; nf++) {
                int col = n0 + wn0 + nf * 8 + 2 * tig;
                float4 v = to_tf32_4(acc[mf][nf]);
                if (!isV) {
                    *(float2*)&g_lk[(size_t)m * 256 + col]       = make_float2(v.x, v.y);
                    *(float2*)&g_lk[(size_t)(m + 8) * 256 + col] = make_float2(v.z, v.w);
                } else {
                    int head = (col - 256) >> 6, d = (col - 256) & 63;
                    int bb2 = m >> 10, gg = m & 1023;
                    size_t base = ((size_t)(bb2 * 4 + head) * 64 + d) * GWIN;
                    g_lvT[base + gg]            = v.x;
                    g_lvT[base + GWIN + gg]     = v.y;
                    g_lvT[base + gg + 8]        = v.z;
                    g_lvT[base + GWIN + gg + 8] = v.w;
                }
            }
        }
    } else {
        // projection: bias + transposed store into (B, 512, 64, 64)
#pragma unroll
        for (int nf = 0; nf < 4; nf++) {
            int n  = wn0 + nf * 8 + 2 * tig;
            float bv0 = bi[n0 + n], bv1 = bi[n0 + n + 1];
            size_t ch0 = (size_t)(co + n0 + n) * HWTOK;
#pragma unroll
            for (int mf = 0; mf < 4; mf++) {
                int m = m0 + wm0 + mf * 16 + g;
                int b0i = m >> 12, tok0 = m & 4095;
                int b1i = (m + 8) >> 12, tok1 = (m + 8) & 4095;
                size_t base0 = (size_t)b0i * (512 * HWTOK);
                size_t base1 = (size_t)b1i * (512 * HWTOK);
                float4 v = acc[mf][nf];
                Cb[base0 + ch0 + tok0]         = v.x + bv0;
                Cb[base0 + ch0 + HWTOK + tok0] = v.y + bv1;
                Cb[base1 + ch0 + tok1]         = v.z + bv0;
                Cb[base1 + ch0 + HWTOK + tok1] = v.w + bv1;
            }
        }
    }
}

// ---------------- hi-fi window attention: one warp per (b, window, head) ----------------
__global__ __launch_bounds__(128) void hi_attn_kernel()
{
    int wgl  = blockIdx.x * 4 + (threadIdx.x >> 5);
    int lane = threadIdx.x & 31;
    int b    = wgl >> 12;
    int rem  = wgl & 4095;
    int g    = rem >> 2;
    int head = rem & 3;
    int gh = g >> 5, gw = g & 31;

    float2 q[4], k[4], v[4];
    int tok[4];
#pragma unroll
    for (int n = 0; n < 4; n++) {
        int hh = gh * 2 + (n >> 1);
        int ww = gw * 2 + (n & 1);
        tok[n] = hh * 64 + ww;
        const float* base = g_qkvq + (size_t)(b * HWTOK + tok[n]) * 1024 + head * 64 + lane * 2;
        q[n] = *(const float2*)(base);
        k[n] = *(const float2*)(base + 256);
        v[n] = *(const float2*)(base + 512);
    }
    float s[4][4];
#pragma unroll
    for (int i = 0; i < 4; i++)
#pragma unroll
        for (int j = 0; j < 4; j++)
            s[i][j] = q[i].x * k[j].x + q[i].y * k[j].y;
#pragma unroll
    for (int off = 16; off; off >>= 1)
#pragma unroll
        for (int i = 0; i < 4; i++)
#pragma unroll
            for (int j = 0; j < 4; j++)
                s[i][j] += __shfl_xor_sync(0xffffffffu, s[i][j], off);

#pragma unroll
    for (int i = 0; i < 4; i++) {
        float s0 = s[i][0] * ATT_SCALE, s1 = s[i][1] * ATT_SCALE;
        float s2 = s[i][2] * ATT_SCALE, s3 = s[i][3] * ATT_SCALE;
        float mx = fmaxf(fmaxf(s0, s1), fmaxf(s2, s3));
        float p0 = __expf(s0 - mx), p1 = __expf(s1 - mx);
        float p2 = __expf(s2 - mx), p3 = __expf(s3 - mx);
        float inv = 1.f / (p0 + p1 + p2 + p3);
        float ox = (p0 * v[0].x + p1 * v[1].x + p2 * v[2].x + p3 * v[3].x) * inv;
        float oy = (p0 * v[0].y + p1 * v[1].y + p2 * v[2].y + p3 * v[3].y) * inv;
        *(float2*)&g_hiat[(size_t)(b * HWTOK + tok[i]) * HDIM + head * 64 + lane * 2] =
            make_float2(to_tf32(ox), to_tf32(oy));
    }
}

// ---------------- lo-fi attention: flash-style tf32 mma + ldmatrix ----------------
#define KVST (64 * LDK)
#define LO_SMEM ((4 * KVST + 128 * LDK) * 4)

__global__ __launch_bounds__(256, 2) void lo_attn_mma()
{
    extern __shared__ float sm[];
    float* Ks = sm;                 // [2][64*LDK]  rows kv, cols d
    float* Vs = sm + 2 * KVST;      // [2][64*LDK]  rows d,  cols kv (transposed)
    float* Ps = sm + 4 * KVST;      // [128*LDK]    Q staging then P

    int bh = blockIdx.y;
    int b = bh >> 2, head = bh & 3;
    int q0 = blockIdx.x * 128;
    int tid  = threadIdx.x;
    int lane = tid & 31, wid = tid >> 5;
    int g = lane >> 2, tig = lane & 3;
    int rr = wid * 16 + g;
    int arow  = lane & 15,               akcol = (lane >> 4) << 2;
    int bnrow = (lane & 7) | ((lane >> 4) << 3), bkcol = ((lane >> 3) & 1) << 2;

    // full 64x64 tile staging: 4 iterations x 256 threads x float4
#define LO_LOAD_KV(ch, st) {                                                              \
    _Pragma("unroll")                                                                     \
    for (int i = 0; i < 4; i++) {                                                         \
        int f = tid + i * 256; int r = f >> 4, dq = (f & 15) * 4;                         \
        cp16(&Ks[(st) * KVST + r * LDK + dq],                                             \
             &g_lk[((size_t)b * GWIN + (ch) * 64 + r) * 256 + head * 64 + dq]);           \
        cp16(&Vs[(st) * KVST + r * LDK + dq],                                             \
             &g_lvT[((size_t)bh * 64 + r) * GWIN + (ch) * 64 + dq]);                      \
    } }

    // stage Q (pre-rounded) via cp.async into Ps
#pragma unroll
    for (int i = 0; i < 8; i++) {
        int f = tid + i * 256;
        int r = f >> 4, dq = (f & 15) * 4;
        cp16(&Ps[r * LDK + dq],
             &g_qkvq[(size_t)(b * HWTOK + q0 + r) * 1024 + 768 + head * 64 + dq]);
    }
    CP_COMMIT;
    LO_LOAD_KV(0, 0);
    CP_COMMIT;
    CP_WAIT1;          // Q group done
    __syncthreads();

    uint32_t qa[8][4];
#pragma unroll
    for (int kf = 0; kf < 8; kf++)
        ldsm4(qa[kf][0], qa[kf][1], qa[kf][2], qa[kf][3],
              &Ps[(wid * 16 + arow) * LDK + kf * 8 + akcol]);

    float4 o[8];
#pragma unroll
    for (int nf = 0; nf < 8; nf++) o[nf] = make_float4(0.f, 0.f, 0.f, 0.f);
    float m_lo = -1e30f, m_hi = -1e30f, l_lo = 0.f, l_hi = 0.f;

#pragma unroll 1
    for (int ch = 0; ch < 16; ch++) {
        if (ch + 1 < 16) { LO_LOAD_KV(ch + 1, (ch + 1) & 1); }
        CP_COMMIT;
        CP_WAIT1;
        __syncthreads();   // also guards qa loads / Ps reuse
        int st = ch & 1;
        const float* Kc = Ks + st * KVST;
        const float* Vc = Vs + st * KVST;

        // ---- S = Q @ K^T (m16 q-rows x n64 kv per warp) ----
        float4 s[8];
#pragma unroll
        for (int nf = 0; nf < 8; nf++) s[nf] = make_float4(0.f, 0.f, 0.f, 0.f);
#pragma unroll
        for (int kf = 0; kf < 8; kf++) {
#pragma unroll
            for (int nfp = 0; nfp < 4; nfp++) {
                uint32_t r0, r1, r2, r3;
                ldsm4(r0, r1, r2, r3, &Kc[(nfp * 16 + bnrow) * LDK + kf * 8 + bkcol]);
                uint32_t b0[2] = {r0, r1}, b1[2] = {r2, r3};
                mma_tf32(s[2 * nfp],     qa[kf], b0);
                mma_tf32(s[2 * nfp + 1], qa[kf], b1);
            }
        }

        // ---- online softmax ----
        float mx_lo = -1e30f, mx_hi = -1e30f;
#pragma unroll
        for (int nf = 0; nf < 8; nf++) {
            s[nf].x *= ATT_SCALE; s[nf].y *= ATT_SCALE;
            s[nf].z *= ATT_SCALE; s[nf].w *= ATT_SCALE;
            mx_lo = fmaxf(mx_lo, fmaxf(s[nf].x, s[nf].y));
            mx_hi = fmaxf(mx_hi, fmaxf(s[nf].z, s[nf].w));
        }
        mx_lo = fmaxf(mx_lo, __shfl_xor_sync(0xffffffffu, mx_lo, 1));
        mx_lo = fmaxf(mx_lo, __shfl_xor_sync(0xffffffffu, mx_lo, 2));
        mx_hi = fmaxf(mx_hi, __shfl_xor_sync(0xffffffffu, mx_hi, 1));
        mx_hi = fmaxf(mx_hi, __shfl_xor_sync(0xffffffffu, mx_hi, 2));

        float mn_lo = fmaxf(m_lo, mx_lo);
        float mn_hi = fmaxf(m_hi, mx_hi);
        float fac_lo = __expf(m_lo - mn_lo);
        float fac_hi = __expf(m_hi - mn_hi);
        m_lo = mn_lo; m_hi = mn_hi;

        float sum_lo = 0.f, sum_hi = 0.f;
#pragma unroll
        for (int nf = 0; nf < 8; nf++) {
            float p0 = __expf(s[nf].x - mn_lo);
            float p1 = __expf(s[nf].y - mn_lo);
            float p2 = __expf(s[nf].z - mn_hi);
            float p3 = __expf(s[nf].w - mn_hi);
            sum_lo += p0 + p1; sum_hi += p2 + p3;
            int col = nf * 8 + 2 * tig;
            *(float2*)&Ps[rr * LDK + col]       = make_float2(to_tf32(p0), to_tf32(p1));
            *(float2*)&Ps[(rr + 8) * LDK + col] = make_float2(to_tf32(p2), to_tf32(p3));
        }
        sum_lo += __shfl_xor_sync(0xffffffffu, sum_lo, 1);
        sum_lo += __shfl_xor_sync(0xffffffffu, sum_lo, 2);
        sum_hi += __shfl_xor_sync(0xffffffffu, sum_hi, 1);
        sum_hi += __shfl_xor_sync(0xffffffffu, sum_hi, 2);
        l_lo = l_lo * fac_lo + sum_lo;
        l_hi = l_hi * fac_hi + sum_hi;

#pragma unroll
        for (int nf = 0; nf < 8; nf++) {
            o[nf].x *= fac_lo; o[nf].y *= fac_lo;
            o[nf].z *= fac_hi; o[nf].w *= fac_hi;
        }
        __syncwarp();   // warp-private Ps rows visible before ldmatrix

        // ---- O += P @ V (m16 x d64 per warp) ----
#pragma unroll
        for (int kf = 0; kf < 8; kf++) {
            uint32_t pa[4];
            ldsm4(pa[0], pa[1], pa[2], pa[3],
                  &Ps[(wid * 16 + arow) * LDK + kf * 8 + akcol]);
#pragma unroll
            for (int nfp = 0; nfp < 4; nfp++) {
                uint32_t r0, r1, r2, r3;
                ldsm4(r0, r1, r2, r3, &Vc[(nfp * 16 + bnrow) * LDK + kf * 8 + bkcol]);
                uint32_t b0[2] = {r0, r1}, b1[2] = {r2, r3};
                mma_tf32(o[2 * nfp],     pa, b0);
                mma_tf32(o[2 * nfp + 1], pa, b1);
            }
        }
        __syncthreads();  // all warps done with Kc/Vc before next overwrite
    }

    float inv_lo = 1.f / l_lo;
    float inv_hi = 1.f / l_hi;
    size_t row0 = (size_t)(b * HWTOK + q0 + rr);
#pragma unroll
    for (int nf = 0; nf < 8; nf++) {
        int col = head * 64 + nf * 8 + 2 * tig;
        *(float2*)&g_loat[row0 * LDIM + col] =
            make_float2(to_tf32(o[nf].x * inv_lo), to_tf32(o[nf].y * inv_lo));
        *(float2*)&g_loat[(row0 + 8) * LDIM + col] =
            make_float2(to_tf32(o[nf].z * inv_hi), to_tf32(o[nf].w * inv_hi));
    }
#undef LO_LOAD_KV
}

// ---------------- launch ----------------
extern "C" void kernel_launch(void* const* d_in, const int* in_sizes, int n_in,
                              void* d_out, int out_size)
{
    (void)in_sizes; (void)n_in; (void)out_size;
    const float* x        = (const float*)d_in[0];
    const float* h_qkv_w  = (const float*)d_in[1];
    const float* h_proj_w = (const float*)d_in[2];
    const float* h_proj_b = (const float*)d_in[3];
    const float* l_q_w    = (const float*)d_in[4];
    const float* l_kv_w   = (const float*)d_in[5];
    const float* l_proj_w = (const float*)d_in[6];
    const float* l_proj_b = (const float*)d_in[7];
    float* out = (float*)d_out;

    float *xr, *wr, *pooled, *qkvq, *lk, *hiat, *loat;
    cudaGetSymbolAddress((void**)&xr,     g_xr);
    cudaGetSymbolAddress((void**)&wr,     g_wr);
    cudaGetSymbolAddress((void**)&pooled, g_pooled);
    cudaGetSymbolAddress((void**)&qkvq,   g_qkvq);
    cudaGetSymbolAddress((void**)&lk,     g_lk);
    cudaGetSymbolAddress((void**)&hiat,   g_hiat);
    cudaGetSymbolAddress((void**)&loat,   g_loat);

    cudaFuncSetAttribute(lo_attn_mma, cudaFuncAttributeMaxDynamicSharedMemorySize, LO_SMEM);
    cudaFuncSetAttribute(gemm_tf32,   cudaFuncAttributeMaxDynamicSharedMemorySize, GEMM_SMEM);

    // 0. transpose + round x and all weights (weights: one launch)
    transpose_round<<<dim3(128, 16, 4), 256>>>(x, xr, CDIM, HWTOK);  // x[b][c][tok] -> [b][tok][c]
    transpose_round_w<<<dim3(24, 16, 5), 256>>>(h_qkv_w, l_q_w, l_kv_w, h_proj_w, l_proj_w);

    // 1. window pooling -> [bg][c] rounded
    pool_kernel<<<dim3(128, 16), 256>>>(x);

    // 2. fused qkv_hi | q_lo GEMM: per batch (4096 x 512) @ (512 x 1024); round cols >= 768
    gemm_tf32<<<dim3(8, 32, 4), 256, GEMM_SMEM>>>(
        xr, CDIM, (size_t)HWTOK * CDIM,
        wr + W_QKV, wr + W_LQ, 768,
        CDIM, qkvq, 1024, (size_t)HWTOK * 1024, 0, 768, nullptr, 0, nullptr, nullptr);

    // 3. lo-fi kv GEMM: (4096 x 512) @ (512 x 512) -> g_lk + g_lvT (transposed V)
    gemm_tf32<<<dim3(4, 32, 1), 256, GEMM_SMEM>>>(
        pooled, CDIM, 0,
        wr + W_LKV, wr + W_LKV, 1 << 30,
        CDIM, lk, 256, 0, 1, 0, nullptr, 0, nullptr, nullptr);

    // 4. hi-fi window attention
    hi_attn_kernel<<<4096, 128>>>();

    // 5. lo-fi attention (tensor-core flash + ldmatrix)
    lo_attn_mma<<<dim3(32, 16), 256, LO_SMEM>>>();

    // 6. both projections in one launch: z=0 hi (channels 0-255), z=1 lo (channels 256-511)
    gemm_tf32<<<dim3(2, 128, 2), 256, GEMM_SMEM>>>(
        hiat, 256, 0, wr + W_HP, wr + W_LP, 1 << 30,
        256, out, 0, 0, 2, 0, h_proj_b, 0, loat, l_proj_b);
}

// round 17
// speedup vs baseline: 1.3424x; 1.3424x over previous
#include <cuda_runtime.h>
#include <math.h>
#include <stdint.h>

// ---------------- problem constants ----------------
#define BATCH   4
#define CDIM    512
#define HWTOK   4096          // 64*64
#define GWIN    1024          // 32*32 windows per batch
#define HDIM    256
#define LDIM    256
#define ATT_SCALE 0.125f      // 64^-0.5

#define LDF 20                // padded row stride (floats) for 16-k GEMM tiles
#define LDK 68                // padded row stride for 64-wide attention tiles
#define GSTG (128 * LDF)      // floats per stage per tensor

// weight scratch offsets (floats) — transposed [n][k] layouts
#define W_QKV 0               // [768][512]
#define W_LQ  393216          // [256][512]
#define W_LKV 524288          // [512][512]
#define W_HP  786432          // [256][256]
#define W_LP  851968          // [256][256]
#define W_TOT 917504

// ---------------- scratch (device globals; no allocation allowed) ----------------
__device__ float g_xr[(size_t)BATCH * HWTOK * CDIM];          // x transposed+rounded: [b][tok][c]
__device__ float g_wr[W_TOT];                                 // transposed+rounded weights
__device__ float g_pooled[BATCH * GWIN * CDIM];               // [bg][c], rounded
__device__ float g_qkvq[(size_t)BATCH * HWTOK * 1024];        // [tok][qkv_hi 768 fp32 | q_lo 256 rounded]
__device__ float g_lk[BATCH * GWIN * 256];                    // lo K: [bg][256], rounded
__device__ float g_lvT[BATCH * 4 * 64 * GWIN];                // lo V transposed: [(b*4+h)*64+d][g], rounded
__device__ float g_hiat[(size_t)BATCH * HWTOK * HDIM];        // hi attn out, rounded
__device__ float g_loat[(size_t)BATCH * HWTOK * LDIM];        // lo attn out, rounded

// ---------------- helpers ----------------
__device__ __forceinline__ float to_tf32(float x) {
    uint32_t r;
    asm("cvt.rna.tf32.f32 %0, %1;" : "=r"(r) : "f"(x));
    return __uint_as_float(r);
}
__device__ __forceinline__ float4 to_tf32_4(float4 v) {
    v.x = to_tf32(v.x); v.y = to_tf32(v.y); v.z = to_tf32(v.z); v.w = to_tf32(v.w);
    return v;
}
__device__ __forceinline__ void cp16(void* dst, const void* src) {
    uint32_t d = (uint32_t)__cvta_generic_to_shared(dst);
    asm volatile("cp.async.cg.shared.global [%0], [%1], 16;\n" :: "r"(d), "l"(src) : "memory");
}
#define CP_COMMIT asm volatile("cp.async.commit_group;\n" ::: "memory")
#define CP_WAIT1  asm volatile("cp.async.wait_group 1;\n" ::: "memory")

__device__ __forceinline__ void ldsm4(uint32_t& r0, uint32_t& r1, uint32_t& r2, uint32_t& r3,
                                      const float* p) {
    uint32_t a = (uint32_t)__cvta_generic_to_shared(p);
    asm volatile("ldmatrix.sync.aligned.m8n8.x4.shared.b16 {%0,%1,%2,%3}, [%4];\n"
                 : "=r"(r0), "=r"(r1), "=r"(r2), "=r"(r3) : "r"(a));
}

// D = A(16x8) * B(8x8) + D, tf32 in, f32 out.
__device__ __forceinline__ void mma_tf32(float4& c, const uint32_t* a, const uint32_t* b) {
    asm volatile(
        "mma.sync.aligned.m16n8k8.row.col.f32.tf32.tf32.f32 "
        "{%0,%1,%2,%3}, {%4,%5,%6,%7}, {%8,%9}, {%0,%1,%2,%3};\n"
        : "+f"(c.x), "+f"(c.y), "+f"(c.z), "+f"(c.w)
        : "r"(a[0]), "r"(a[1]), "r"(a[2]), "r"(a[3]), "r"(b[0]), "r"(b[1]));
}

// ---------------- tiled transpose + tf32 round: in[r][c] -> out[c][r] ----------------
__global__ void transpose_round(const float* __restrict__ in, float* __restrict__ out,
                                int rows, int cols)
{
    __shared__ float t[32][33];
    size_t plane = (size_t)rows * cols;
    in  += (size_t)blockIdx.z * plane;
    out += (size_t)blockIdx.z * plane;
    int c0 = blockIdx.x * 32, r0 = blockIdx.y * 32;
    int tx = threadIdx.x & 31, ty = threadIdx.x >> 5;
#pragma unroll
    for (int i = 0; i < 4; i++)
        t[ty + i * 8][tx] = to_tf32(in[(size_t)(r0 + ty + i * 8) * cols + c0 + tx]);
    __syncthreads();
#pragma unroll
    for (int i = 0; i < 4; i++)
        out[(size_t)(c0 + ty + i * 8) * rows + r0 + tx] = t[tx][ty + i * 8];
}

// ---------------- all 5 weight transposes in one launch (z-indexed) ----------------
__global__ void transpose_round_w(const float* __restrict__ w1, const float* __restrict__ w2,
                                  const float* __restrict__ w3, const float* __restrict__ w4,
                                  const float* __restrict__ w5)
{
    __shared__ float t[32][33];
    const float* in; float* out; int rows, cols;
    switch (blockIdx.z) {
        case 0:  in = w1; out = g_wr + W_QKV; rows = CDIM; cols = 768; break;
        case 1:  in = w2; out = g_wr + W_LQ;  rows = CDIM; cols = 256; break;
        case 2:  in = w3; out = g_wr + W_LKV; rows = CDIM; cols = 512; break;
        case 3:  in = w4; out = g_wr + W_HP;  rows = 256;  cols = 256; break;
        default: in = w5; out = g_wr + W_LP;  rows = 256;  cols = 256; break;
    }
    int c0 = blockIdx.x * 32, r0 = blockIdx.y * 32;
    if (c0 >= cols || r0 >= rows) return;
    int tx = threadIdx.x & 31, ty = threadIdx.x >> 5;
#pragma unroll
    for (int i = 0; i < 4; i++)
        t[ty + i * 8][tx] = to_tf32(in[(size_t)(r0 + ty + i * 8) * cols + c0 + tx]);
    __syncthreads();
#pragma unroll
    for (int i = 0; i < 4; i++)
        out[(size_t)(c0 + ty + i * 8) * rows + r0 + tx] = t[tx][ty + i * 8];
}

// ---------------- window pooling -> g_pooled [bg][c], rounded ----------------
__global__ void pool_kernel(const float* __restrict__ x)
{
    __shared__ float t[32][33];
    int bg0 = blockIdx.x * 32, c0 = blockIdx.y * 32;
    int tx = threadIdx.x & 31, ty = threadIdx.x >> 5;
    int b = bg0 >> 10;
    int gbase = bg0 & 1023;
#pragma unroll
    for (int i = 0; i < 4; i++) {
        int c = c0 + ty + i * 8;
        int g = gbase + tx;
        int gh = g >> 5, gw = g & 31;
        const float* p = x + ((size_t)b * CDIM + c) * HWTOK + gh * 128 + gw * 2;
        t[ty + i * 8][tx] = to_tf32(0.25f * (p[0] + p[1] + p[64] + p[65]));
    }
    __syncthreads();
#pragma unroll
    for (int i = 0; i < 4; i++) {
        int bg = bg0 + ty + i * 8;
        g_pooled[(size_t)bg * CDIM + c0 + tx] = t[tx][ty + i * 8];
    }
}

// ---------------- tf32 GEMM, 2-stage cp.async + ldmatrix (round-15 proven config) ----------------
// A row-major [m][K] pre-rounded. B row-major [n][K] pre-rounded (transposed weights).
// 128x128 tile, K-slab 16, 256 threads = 8 warps (2m x 4n), warp tile 64x32.
// mode 0: C row-major, round cols >= roundCol
// mode 1: lo-kv: cols<256 -> g_lk[m][col]; cols>=256 -> g_lvT transposed (all rounded)
// mode 2: dual projection (z=0: A/B1/bias/cOff=0; z=1: A2/B2/bias2/cOff=256),
//         bias + transposed store into (B,512,64,64)
__global__ __launch_bounds__(256) void gemm_tf32(
    const float* __restrict__ A, int lda, size_t aBatch,
    const float* __restrict__ B1, const float* __restrict__ B2, int nsplit,
    int K, float* __restrict__ C, int ldc, size_t cBatch,
    int mode, int roundCol, const float* __restrict__ bias, int cOff,
    const float* __restrict__ A2, const float* __restrict__ bias2)
{
    __shared__ float As[2][GSTG];
    __shared__ float Bs[2][GSTG];

    int n0 = blockIdx.x * 128, m0 = blockIdx.y * 128;
    const float* Ab; float* Cb; const float* Bw; int nb;
    const float* bi = bias; int co = cOff;
    if (mode == 2) {
        Cb = C; nb = n0;
        if (blockIdx.z == 0) { Ab = A;  Bw = B1; }
        else                 { Ab = A2; Bw = B2; bi = bias2; co = 256; }
    } else {
        Ab = A + (size_t)blockIdx.z * aBatch;
        Cb = C + (size_t)blockIdx.z * cBatch;
        if (n0 < nsplit) { Bw = B1; nb = n0; }
        else             { Bw = B2; nb = n0 - nsplit; }
    }

    int tid  = threadIdx.x;
    int lane = tid & 31, wid = tid >> 5;
    int g = lane >> 2, tig = lane & 3;
    int wm0 = (wid & 1) * 64;
    int wn0 = (wid >> 1) * 32;
    // ldmatrix lane addressing
    int arow  = lane & 15,               akcol = (lane >> 4) << 2;               // A (m16 x k8)
    int bnrow = (lane & 7) | ((lane >> 4) << 3), bkcol = ((lane >> 3) & 1) << 2; // B (n16 x k8)
    // staging
    int sm = tid >> 2, skq = (tid & 3) * 4;

    float4 acc[4][4];
#pragma unroll
    for (int i = 0; i < 4; i++)
#pragma unroll
        for (int j = 0; j < 4; j++) acc[i][j] = make_float4(0.f, 0.f, 0.f, 0.f);

#define STAGE(k0, st) {                                                                  \
    cp16(&As[st][sm * LDF + skq],        &Ab[(size_t)(m0 + sm) * lda + (k0) + skq]);     \
    cp16(&As[st][(sm + 64) * LDF + skq], &Ab[(size_t)(m0 + sm + 64) * lda + (k0) + skq]);\
    cp16(&Bs[st][sm * LDF + skq],        &Bw[(size_t)(nb + sm) * K + (k0) + skq]);       \
    cp16(&Bs[st][(sm + 64) * LDF + skq], &Bw[(size_t)(nb + sm + 64) * K + (k0) + skq]); }

    int nIter = K >> 4;
    STAGE(0, 0);
    CP_COMMIT;

#pragma unroll 1
    for (int it = 0; it < nIter; it++) {
        if (it + 1 < nIter) { int k0 = (it + 1) << 4; STAGE(k0, (it + 1) & 1); }
        CP_COMMIT;
        CP_WAIT1;
        __syncthreads();
        const float* Ac = As[it & 1];
        const float* Bc = Bs[it & 1];
#pragma unroll
        for (int ks = 0; ks < 16; ks += 8) {
            uint32_t a[4][4], b[4][2];
#pragma unroll
            for (int mf = 0; mf < 4; mf++)
                ldsm4(a[mf][0], a[mf][1], a[mf][2], a[mf][3],
                      &Ac[(wm0 + mf * 16 + arow) * LDF + ks + akcol]);
#pragma unroll
            for (int nfp = 0; nfp < 2; nfp++) {
                uint32_t r0, r1, r2, r3;
                ldsm4(r0, r1, r2, r3, &Bc[(wn0 + nfp * 16 + bnrow) * LDF + ks + bkcol]);
                b[2 * nfp][0] = r0; b[2 * nfp][1] = r1;
                b[2 * nfp + 1][0] = r2; b[2 * nfp + 1][1] = r3;
            }
#pragma unroll
            for (int mf = 0; mf < 4; mf++)
#pragma unroll
                for (int nf = 0; nf < 4; nf++)
                    mma_tf32(acc[mf][nf], a[mf], b[nf]);
        }
        __syncthreads();
    }
#undef STAGE

    if (mode == 0) {
        bool doRound = (n0 >= roundCol);
#pragma unroll
        for (int mf = 0; mf < 4; mf++) {
            int row = m0 + wm0 + mf * 16 + g;
#pragma unroll
            for (int nf = 0; nf < 4; nf++) {
                int col = n0 + wn0 + nf * 8 + 2 * tig;
                float4 v = acc[mf][nf];
                if (doRound) v = to_tf32_4(v);
                *(float2*)&Cb[(size_t)row * ldc + col]       = make_float2(v.x, v.y);
                *(float2*)&Cb[(size_t)(row + 8) * ldc + col] = make_float2(v.z, v.w);
            }
        }
    } else if (mode == 1) {
        bool isV = (n0 >= 256);
#pragma unroll
        for (int mf = 0; mf < 4; mf++) {
            int m = m0 + wm0 + mf * 16 + g;
#pragma unroll
            for (int nf = 0; nf < 4; nf++) {
                int col = n0 + wn0 + nf * 8 + 2 * tig;
                float4 v = to_tf32_4(acc[mf][nf]);
                if (!isV) {
                    *(float2*)&g_lk[(size_t)m * 256 + col]       = make_float2(v.x, v.y);
                    *(float2*)&g_lk[(size_t)(m + 8) * 256 + col] = make_float2(v.z, v.w);
                } else {
                    int head = (col - 256) >> 6, d = (col - 256) & 63;
                    int bb2 = m >> 10, gg = m & 1023;
                    size_t base = ((size_t)(bb2 * 4 + head) * 64 + d) * GWIN;
                    g_lvT[base + gg]            = v.x;
                    g_lvT[base + GWIN + gg]     = v.y;
                    g_lvT[base + gg + 8]        = v.z;
                    g_lvT[base + GWIN + gg + 8] = v.w;
                }
            }
        }
    } else {
        // projection: bias + transposed store into (B, 512, 64, 64)
#pragma unroll
        for (int nf = 0; nf < 4; nf++) {
            int n  = wn0 + nf * 8 + 2 * tig;
            float bv0 = bi[n0 + n], bv1 = bi[n0 + n + 1];
            size_t ch0 = (size_t)(co + n0 + n) * HWTOK;
#pragma unroll
            for (int mf = 0; mf < 4; mf++) {
                int m = m0 + wm0 + mf * 16 + g;
                int b0i = m >> 12, tok0 = m & 4095;
                int b1i = (m + 8) >> 12, tok1 = (m + 8) & 4095;
                size_t base0 = (size_t)b0i * (512 * HWTOK);
                size_t base1 = (size_t)b1i * (512 * HWTOK);
                float4 v = acc[mf][nf];
                Cb[base0 + ch0 + tok0]         = v.x + bv0;
                Cb[base0 + ch0 + HWTOK + tok0] = v.y + bv1;
                Cb[base1 + ch0 + tok1]         = v.z + bv0;
                Cb[base1 + ch0 + HWTOK + tok1] = v.w + bv1;
            }
        }
    }
}

// ---------------- hi-fi window attention: one warp per (b, window, head) ----------------
__global__ __launch_bounds__(128) void hi_attn_kernel()
{
    int wgl  = blockIdx.x * 4 + (threadIdx.x >> 5);
    int lane = threadIdx.x & 31;
    int b    = wgl >> 12;
    int rem  = wgl & 4095;
    int g    = rem >> 2;
    int head = rem & 3;
    int gh = g >> 5, gw = g & 31;

    float2 q[4], k[4], v[4];
    int tok[4];
#pragma unroll
    for (int n = 0; n < 4; n++) {
        int hh = gh * 2 + (n >> 1);
        int ww = gw * 2 + (n & 1);
        tok[n] = hh * 64 + ww;
        const float* base = g_qkvq + (size_t)(b * HWTOK + tok[n]) * 1024 + head * 64 + lane * 2;
        q[n] = *(const float2*)(base);
        k[n] = *(const float2*)(base + 256);
        v[n] = *(const float2*)(base + 512);
    }
    float s[4][4];
#pragma unroll
    for (int i = 0; i < 4; i++)
#pragma unroll
        for (int j = 0; j < 4; j++)
            s[i][j] = q[i].x * k[j].x + q[i].y * k[j].y;
#pragma unroll
    for (int off = 16; off; off >>= 1)
#pragma unroll
        for (int i = 0; i < 4; i++)
#pragma unroll
            for (int j = 0; j < 4; j++)
                s[i][j] += __shfl_xor_sync(0xffffffffu, s[i][j], off);

#pragma unroll
    for (int i = 0; i < 4; i++) {
        float s0 = s[i][0] * ATT_SCALE, s1 = s[i][1] * ATT_SCALE;
        float s2 = s[i][2] * ATT_SCALE, s3 = s[i][3] * ATT_SCALE;
        float mx = fmaxf(fmaxf(s0, s1), fmaxf(s2, s3));
        float p0 = __expf(s0 - mx), p1 = __expf(s1 - mx);
        float p2 = __expf(s2 - mx), p3 = __expf(s3 - mx);
        float inv = 1.f / (p0 + p1 + p2 + p3);
        float ox = (p0 * v[0].x + p1 * v[1].x + p2 * v[2].x + p3 * v[3].x) * inv;
        float oy = (p0 * v[0].y + p1 * v[1].y + p2 * v[2].y + p3 * v[3].y) * inv;
        *(float2*)&g_hiat[(size_t)(b * HWTOK + tok[i]) * HDIM + head * 64 + lane * 2] =
            make_float2(to_tf32(ox), to_tf32(oy));
    }
}

// ---------------- lo-fi attention: flash-style tf32 mma + ldmatrix ----------------
#define KVST (64 * LDK)
#define LO_SMEM ((4 * KVST + 128 * LDK) * 4)

__global__ __launch_bounds__(256, 2) void lo_attn_mma()
{
    extern __shared__ float sm[];
    float* Ks = sm;                 // [2][64*LDK]  rows kv, cols d
    float* Vs = sm + 2 * KVST;      // [2][64*LDK]  rows d,  cols kv (transposed)
    float* Ps = sm + 4 * KVST;      // [128*LDK]    Q staging then P

    int bh = blockIdx.y;
    int b = bh >> 2, head = bh & 3;
    int q0 = blockIdx.x * 128;
    int tid  = threadIdx.x;
    int lane = tid & 31, wid = tid >> 5;
    int g = lane >> 2, tig = lane & 3;
    int rr = wid * 16 + g;
    int arow  = lane & 15,               akcol = (lane >> 4) << 2;
    int bnrow = (lane & 7) | ((lane >> 4) << 3), bkcol = ((lane >> 3) & 1) << 2;

    // full 64x64 tile staging: 4 iterations x 256 threads x float4
#define LO_LOAD_KV(ch, st) {                                                              \
    _Pragma("unroll")                                                                     \
    for (int i = 0; i < 4; i++) {                                                         \
        int f = tid + i * 256; int r = f >> 4, dq = (f & 15) * 4;                         \
        cp16(&Ks[(st) * KVST + r * LDK + dq],                                             \
             &g_lk[((size_t)b * GWIN + (ch) * 64 + r) * 256 + head * 64 + dq]);           \
        cp16(&Vs[(st) * KVST + r * LDK + dq],                                             \
             &g_lvT[((size_t)bh * 64 + r) * GWIN + (ch) * 64 + dq]);                      \
    } }

    // stage Q (pre-rounded) via cp.async into Ps
#pragma unroll
    for (int i = 0; i < 8; i++) {
        int f = tid + i * 256;
        int r = f >> 4, dq = (f & 15) * 4;
        cp16(&Ps[r * LDK + dq],
             &g_qkvq[(size_t)(b * HWTOK + q0 + r) * 1024 + 768 + head * 64 + dq]);
    }
    CP_COMMIT;
    LO_LOAD_KV(0, 0);
    CP_COMMIT;
    CP_WAIT1;          // Q group done
    __syncthreads();

    uint32_t qa[8][4];
#pragma unroll
    for (int kf = 0; kf < 8; kf++)
        ldsm4(qa[kf][0], qa[kf][1], qa[kf][2], qa[kf][3],
              &Ps[(wid * 16 + arow) * LDK + kf * 8 + akcol]);

    float4 o[8];
#pragma unroll
    for (int nf = 0; nf < 8; nf++) o[nf] = make_float4(0.f, 0.f, 0.f, 0.f);
    float m_lo = -1e30f, m_hi = -1e30f, l_lo = 0.f, l_hi = 0.f;

#pragma unroll 1
    for (int ch = 0; ch < 16; ch++) {
        if (ch + 1 < 16) { LO_LOAD_KV(ch + 1, (ch + 1) & 1); }
        CP_COMMIT;
        CP_WAIT1;
        __syncthreads();   // also guards qa loads / Ps reuse
        int st = ch & 1;
        const float* Kc = Ks + st * KVST;
        const float* Vc = Vs + st * KVST;

        // ---- S = Q @ K^T (m16 q-rows x n64 kv per warp) ----
        float4 s[8];
#pragma unroll
        for (int nf = 0; nf < 8; nf++) s[nf] = make_float4(0.f, 0.f, 0.f, 0.f);
#pragma unroll
        for (int kf = 0; kf < 8; kf++) {
#pragma unroll
            for (int nfp = 0; nfp < 4; nfp++) {
                uint32_t r0, r1, r2, r3;
                ldsm4(r0, r1, r2, r3, &Kc[(nfp * 16 + bnrow) * LDK + kf * 8 + bkcol]);
                uint32_t b0[2] = {r0, r1}, b1[2] = {r2, r3};
                mma_tf32(s[2 * nfp],     qa[kf], b0);
                mma_tf32(s[2 * nfp + 1], qa[kf], b1);
            }
        }

        // ---- online softmax ----
        float mx_lo = -1e30f, mx_hi = -1e30f;
#pragma unroll
        for (int nf = 0; nf < 8; nf++) {
            s[nf].x *= ATT_SCALE; s[nf].y *= ATT_SCALE;
            s[nf].z *= ATT_SCALE; s[nf].w *= ATT_SCALE;
            mx_lo = fmaxf(mx_lo, fmaxf(s[nf].x, s[nf].y));
            mx_hi = fmaxf(mx_hi, fmaxf(s[nf].z, s[nf].w));
        }
        mx_lo = fmaxf(mx_lo, __shfl_xor_sync(0xffffffffu, mx_lo, 1));
        mx_lo = fmaxf(mx_lo, __shfl_xor_sync(0xffffffffu, mx_lo, 2));
        mx_hi = fmaxf(mx_hi, __shfl_xor_sync(0xffffffffu, mx_hi, 1));
        mx_hi = fmaxf(mx_hi, __shfl_xor_sync(0xffffffffu, mx_hi, 2));

        float mn_lo = fmaxf(m_lo, mx_lo);
        float mn_hi = fmaxf(m_hi, mx_hi);
        float fac_lo = __expf(m_lo - mn_lo);
        float fac_hi = __expf(m_hi - mn_hi);
        m_lo = mn_lo; m_hi = mn_hi;

        float sum_lo = 0.f, sum_hi = 0.f;
#pragma unroll
        for (int nf = 0; nf < 8; nf++) {
            float p0 = __expf(s[nf].x - mn_lo);
            float p1 = __expf(s[nf].y - mn_lo);
            float p2 = __expf(s[nf].z - mn_hi);
            float p3 = __expf(s[nf].w - mn_hi);
            sum_lo += p0 + p1; sum_hi += p2 + p3;
            int col = nf * 8 + 2 * tig;
            *(float2*)&Ps[rr * LDK + col]       = make_float2(to_tf32(p0), to_tf32(p1));
            *(float2*)&Ps[(rr + 8) * LDK + col] = make_float2(to_tf32(p2), to_tf32(p3));
        }
        sum_lo += __shfl_xor_sync(0xffffffffu, sum_lo, 1);
        sum_lo += __shfl_xor_sync(0xffffffffu, sum_lo, 2);
        sum_hi += __shfl_xor_sync(0xffffffffu, sum_hi, 1);
        sum_hi += __shfl_xor_sync(0xffffffffu, sum_hi, 2);
        l_lo = l_lo * fac_lo + sum_lo;
        l_hi = l_hi * fac_hi + sum_hi;

#pragma unroll
        for (int nf = 0; nf < 8; nf++) {
            o[nf].x *= fac_lo; o[nf].y *= fac_lo;
            o[nf].z *= fac_hi; o[nf].w *= fac_hi;
        }
        __syncwarp();   // warp-private Ps rows visible before ldmatrix

        // ---- O += P @ V (m16 x d64 per warp) ----
#pragma unroll
        for (int kf = 0; kf < 8; kf++) {
            uint32_t pa[4];
            ldsm4(pa[0], pa[1], pa[2], pa[3],
                  &Ps[(wid * 16 + arow) * LDK + kf * 8 + akcol]);
#pragma unroll
            for (int nfp = 0; nfp < 4; nfp++) {
                uint32_t r0, r1, r2, r3;
                ldsm4(r0, r1, r2, r3, &Vc[(nfp * 16 + bnrow) * LDK + kf * 8 + bkcol]);
                uint32_t b0[2] = {r0, r1}, b1[2] = {r2, r3};
                mma_tf32(o[2 * nfp],     pa, b0);
                mma_tf32(o[2 * nfp + 1], pa, b1);
            }
        }
        __syncthreads();  // all warps done with Kc/Vc before next overwrite
    }

    float inv_lo = 1.f / l_lo;
    float inv_hi = 1.f / l_hi;
    size_t row0 = (size_t)(b * HWTOK + q0 + rr);
#pragma unroll
    for (int nf = 0; nf < 8; nf++) {
        int col = head * 64 + nf * 8 + 2 * tig;
        *(float2*)&g_loat[row0 * LDIM + col] =
            make_float2(to_tf32(o[nf].x * inv_lo), to_tf32(o[nf].y * inv_lo));
        *(float2*)&g_loat[(row0 + 8) * LDIM + col] =
            make_float2(to_tf32(o[nf].z * inv_hi), to_tf32(o[nf].w * inv_hi));
    }
#undef LO_LOAD_KV
}

// ---------------- launch ----------------
extern "C" void kernel_launch(void* const* d_in, const int* in_sizes, int n_in,
                              void* d_out, int out_size)
{
    (void)in_sizes; (void)n_in; (void)out_size;
    const float* x        = (const float*)d_in[0];
    const float* h_qkv_w  = (const float*)d_in[1];
    const float* h_proj_w = (const float*)d_in[2];
    const float* h_proj_b = (const float*)d_in[3];
    const float* l_q_w    = (const float*)d_in[4];
    const float* l_kv_w   = (const float*)d_in[5];
    const float* l_proj_w = (const float*)d_in[6];
    const float* l_proj_b = (const float*)d_in[7];
    float* out = (float*)d_out;

    float *xr, *wr, *pooled, *qkvq, *lk, *hiat, *loat;
    cudaGetSymbolAddress((void**)&xr,     g_xr);
    cudaGetSymbolAddress((void**)&wr,     g_wr);
    cudaGetSymbolAddress((void**)&pooled, g_pooled);
    cudaGetSymbolAddress((void**)&qkvq,   g_qkvq);
    cudaGetSymbolAddress((void**)&lk,     g_lk);
    cudaGetSymbolAddress((void**)&hiat,   g_hiat);
    cudaGetSymbolAddress((void**)&loat,   g_loat);

    cudaFuncSetAttribute(lo_attn_mma, cudaFuncAttributeMaxDynamicSharedMemorySize, LO_SMEM);

    // 0. transpose + round x and all weights (weights: one launch)
    transpose_round<<<dim3(128, 16, 4), 256>>>(x, xr, CDIM, HWTOK);  // x[b][c][tok] -> [b][tok][c]
    transpose_round_w<<<dim3(24, 16, 5), 256>>>(h_qkv_w, l_q_w, l_kv_w, h_proj_w, l_proj_w);

    // 1. window pooling -> [bg][c] rounded
    pool_kernel<<<dim3(128, 16), 256>>>(x);

    // 2. fused qkv_hi | q_lo GEMM: per batch (4096 x 512) @ (512 x 1024); round cols >= 768
    gemm_tf32<<<dim3(8, 32, 4), 256>>>(
        xr, CDIM, (size_t)HWTOK * CDIM,
        wr + W_QKV, wr + W_LQ, 768,
        CDIM, qkvq, 1024, (size_t)HWTOK * 1024, 0, 768, nullptr, 0, nullptr, nullptr);

    // 3. lo-fi kv GEMM: (4096 x 512) @ (512 x 512) -> g_lk + g_lvT (transposed V)
    gemm_tf32<<<dim3(4, 32, 1), 256>>>(
        pooled, CDIM, 0,
        wr + W_LKV, wr + W_LKV, 1 << 30,
        CDIM, lk, 256, 0, 1, 0, nullptr, 0, nullptr, nullptr);

    // 4. hi-fi window attention
    hi_attn_kernel<<<4096, 128>>>();

    // 5. lo-fi attention (tensor-core flash + ldmatrix)
    lo_attn_mma<<<dim3(32, 16), 256, LO_SMEM>>>();

    // 6. both projections in one launch: z=0 hi (channels 0-255), z=1 lo (channels 256-511)
    gemm_tf32<<<dim3(2, 128, 2), 256>>>(
        hiat, 256, 0, wr + W_HP, wr + W_LP, 1 << 30,
        256, out, 0, 0, 2, 0, h_proj_b, 0, loat, l_proj_b);
}